// round 13
// baseline (speedup 1.0000x reference)
#include <cuda_runtime.h>
#include <cstdint>
#include <math_constants.h>

// KineticOptimalDiscreteEulerSolver — closed-form collapse, single-wave version.
//
// Inputs: d_in[0] logits f32[64*1024], d_in[1] source_p f32[1024],
//         d_in[2] x_t i32[64], d_in[3] t f32[1].  Output f32[64*1024].
//
// Algebra: clamped antisymmetric-flux row at i = x_t has <= 2 nonzeros:
//   x_t == x1 : all zeros
//   x_t != x1 : out[x1] = sp[x_t] / ((1-k)*sp[x1] + k + EPS), out[x_t] = -out[x1]
// x1 = argmax(logits + gumbel) = jax.random.categorical(key(1), logits),
// PARTITIONABLE threefry (verified R6/R8): counter (0, e), bits = out0 ^ out1.
//
// Layout: 2 blocks/token x 512 threads (grid=128 <= 148 SMs: ONE wave),
// 1 element/thread. Argmax reduced as a packed u64 key
// (ordered_float(val)<<32 | 1023-idx): order-independent max, ties -> lower
// index (jnp.argmax). Cross-block: atomicMax + ticket; last block finalizes
// and resets scratch (replay-deterministic under graph capture).

#define V        1024
#define NTOK     64
#define QPT      2          // blocks per token
#define BT       512        // threads per block
#define EPSV     1e-8f
#define TINYF    1.17549435e-38f

__device__ unsigned long long g_amax[NTOK];  // zero at load; reset each launch
__device__ unsigned int       g_cnt[NTOK];

__device__ __forceinline__ uint32_t rotl32(uint32_t x, uint32_t r) {
    return (x << r) | (x >> (32u - r));
}

// JAX threefry2x32, key = (0,1), returns out0 ^ out1 (partitionable reduction).
__device__ __forceinline__ uint32_t threefry_xor_0_1(uint32_t x0, uint32_t x1) {
    const uint32_t ks0 = 0u, ks1 = 1u;
    const uint32_t ks2 = 0x1BD11BDAu ^ ks0 ^ ks1;   // 0x1BD11BDB
    x0 += ks0; x1 += ks1;
#define TF_RND(r) { x0 += x1; x1 = rotl32(x1, r); x1 ^= x0; }
    TF_RND(13) TF_RND(15) TF_RND(26) TF_RND(6)
    x0 += ks1; x1 += ks2 + 1u;
    TF_RND(17) TF_RND(29) TF_RND(16) TF_RND(24)
    x0 += ks2; x1 += ks0 + 2u;
    TF_RND(13) TF_RND(15) TF_RND(26) TF_RND(6)
    x0 += ks0; x1 += ks1 + 3u;
    TF_RND(17) TF_RND(29) TF_RND(16) TF_RND(24)
    x0 += ks1; x1 += ks2 + 4u;
    TF_RND(13) TF_RND(15) TF_RND(26) TF_RND(6)
    x0 += ks2; x1 += ks0 + 5u;
#undef TF_RND
    return x0 ^ x1;
}

// Gumbel for flat element e. Fast MUFU logs (__logf): only the argmax must
// survive, and ulp-level gumbel noise flips it only on ~1e-5 near-ties.
__device__ __forceinline__ float jax_gumbel(uint32_t e) {
    uint32_t bits = threefry_xor_0_1(0u, e);
    float f = __uint_as_float((bits >> 9) | 0x3F800000u) - 1.0f;
    float u = fmaxf(TINYF, f * (1.0f - TINYF) + TINYF);
    return -__logf(-__logf(u));
}

__global__ void __launch_bounds__(BT, 1)
kinetic_euler_kernel(const float* __restrict__ logits,
                     const float* __restrict__ source_p,
                     const int*   __restrict__ x_t,
                     const float* __restrict__ t,
                     float*       __restrict__ out) {
    const int bid  = blockIdx.x;
    const int n    = bid >> 1;       // token
    const int q    = bid & 1;        // half of the row
    const int tid  = threadIdx.x;    // 0..511
    const int wid  = tid >> 5;       // 0..15
    const int lane = tid & 31;

    __shared__ unsigned long long wKey[16];
    __shared__ float              wSum[16];

    const float* lrow = logits + n * V;
    float*       orow = out    + n * V;
    const int    v    = q * BT + tid;

    // zero-fill this block's half of the output row
    orow[v] = 0.0f;

    // full source_p sum, replicated per block (identical order => same S)
    float psum = source_p[tid] + source_p[tid + BT];

    // one gumbel per thread; pack argmax candidate into order-preserving u64
    float val = lrow[v] + jax_gumbel((uint32_t)(n * V + v));
    uint32_t ov = __float_as_uint(val);
    ov = (ov & 0x80000000u) ? ~ov : (ov | 0x80000000u);   // monotone map
    unsigned long long key =
        ((unsigned long long)ov << 32) | (unsigned int)(V - 1 - v);

    // warp reduce: u64 max + float sum
#pragma unroll
    for (int off = 16; off > 0; off >>= 1) {
        unsigned long long k2 = __shfl_xor_sync(0xFFFFFFFFu, key, off);
        if (k2 > key) key = k2;
        psum += __shfl_xor_sync(0xFFFFFFFFu, psum, off);
    }
    if (lane == 0) { wKey[wid] = key; wSum[wid] = psum; }
    __syncthreads();

    // warp 0 reduces the 16 per-warp partials
    if (wid == 0) {
        key  = (lane < 16) ? wKey[lane] : 0ULL;
        psum = (lane < 16) ? wSum[lane] : 0.0f;
#pragma unroll
        for (int off = 8; off > 0; off >>= 1) {
            unsigned long long k2 = __shfl_xor_sync(0xFFFFFFFFu, key, off);
            if (k2 > key) key = k2;
            psum += __shfl_xor_sync(0xFFFFFFFFu, psum, off);
        }
        if (lane == 0) {
            float S = psum;
            atomicMax(&g_amax[n], key);
            __threadfence();                   // publish zero-fill + max
            unsigned int old = atomicAdd(&g_cnt[n], 1u);
            if (old == QPT - 1) {              // last block for this token
                __threadfence();
                unsigned long long kk =
                    *(volatile unsigned long long*)&g_amax[n];
                int x1  = V - 1 - (int)(kk & 0xFFFFFFFFu);
                int xti = __ldg(x_t + n);
                if (x1 != xti) {
                    float k  = __ldg(t);
                    float si = __ldg(source_p + xti) / S;      // sp[x_t]
                    float sj = __ldg(source_p + x1)  / S;      // sp[x1]
                    float denom = (1.0f - k) * sj + k + EPSV;  // p_t[x1]+EPS
                    float w = si / denom;
                    orow[x1]  = w;     // off-diagonal jump rate
                    orow[xti] = -w;    // diagonal correction
                }
                // reset scratch for next graph replay (no writers remain)
                g_amax[n] = 0ULL;
                g_cnt[n]  = 0u;
            }
        }
    }
}

extern "C" void kernel_launch(void* const* d_in, const int* in_sizes, int n_in,
                              void* d_out, int out_size) {
    const float* logits   = (const float*)d_in[0];
    const float* source_p = (const float*)d_in[1];
    const int*   x_t      = (const int*)  d_in[2];
    const float* t        = (const float*)d_in[3];
    float*       out      = (float*)d_out;
    kinetic_euler_kernel<<<NTOK * QPT, BT>>>(logits, source_p, x_t, t, out);
}

// round 17
// speedup vs baseline: 1.2605x; 1.2605x over previous
#include <cuda_runtime.h>
#include <cstdint>
#include <math_constants.h>

// KineticOptimalDiscreteEulerSolver — closed-form collapse, block-local version.
//
// Inputs: d_in[0] logits f32[64*1024], d_in[1] source_p f32[1024],
//         d_in[2] x_t i32[64], d_in[3] t f32[1].  Output f32[64*1024].
//
// Algebra: clamped antisymmetric-flux row at i = x_t has <= 2 nonzeros:
//   x_t == x1 : all zeros
//   x_t != x1 : out[x1] = sp[x_t] / ((1-k)*sp[x1] + k + EPS), out[x_t] = -out[x1]
// x1 = argmax(logits + gumbel) = jax.random.categorical(key(1), logits),
// PARTITIONABLE threefry (verified R6/R8/R13): counter (0, e), bits = o0 ^ o1.
//
// Layout: 1 block/token x 512 threads (grid=64), 2 elements/thread with two
// INDEPENDENT gumbel chains (ILP, not serialization). Everything block-local:
// no global atomics, no fences, no cross-CTA skew — removes the ~1us
// rendezvous tail that R8/R13 both paid. Argmax as packed u64
// (ordered_float<<32 | 1023-idx): ties -> lower index (jnp.argmax).

#define V        1024
#define NTOK     64
#define BT       512        // threads per block
#define EPSV     1e-8f
#define TINYF    1.17549435e-38f

__device__ __forceinline__ uint32_t rotl32(uint32_t x, uint32_t r) {
    return (x << r) | (x >> (32u - r));
}

// JAX threefry2x32, key = (0,1), returns out0 ^ out1 (partitionable reduction).
__device__ __forceinline__ uint32_t threefry_xor_0_1(uint32_t x0, uint32_t x1) {
    const uint32_t ks0 = 0u, ks1 = 1u;
    const uint32_t ks2 = 0x1BD11BDAu ^ ks0 ^ ks1;   // 0x1BD11BDB
    x0 += ks0; x1 += ks1;
#define TF_RND(r) { x0 += x1; x1 = rotl32(x1, r); x1 ^= x0; }
    TF_RND(13) TF_RND(15) TF_RND(26) TF_RND(6)
    x0 += ks1; x1 += ks2 + 1u;
    TF_RND(17) TF_RND(29) TF_RND(16) TF_RND(24)
    x0 += ks2; x1 += ks0 + 2u;
    TF_RND(13) TF_RND(15) TF_RND(26) TF_RND(6)
    x0 += ks0; x1 += ks1 + 3u;
    TF_RND(17) TF_RND(29) TF_RND(16) TF_RND(24)
    x0 += ks1; x1 += ks2 + 4u;
    TF_RND(13) TF_RND(15) TF_RND(26) TF_RND(6)
    x0 += ks2; x1 += ks0 + 5u;
#undef TF_RND
    return x0 ^ x1;
}

// Gumbel for flat element e. MUFU fast logs (verified harmless in R13:
// rel_err bit-identical to the precise-log run).
__device__ __forceinline__ float jax_gumbel(uint32_t e) {
    uint32_t bits = threefry_xor_0_1(0u, e);
    float f = __uint_as_float((bits >> 9) | 0x3F800000u) - 1.0f;
    float u = fmaxf(TINYF, f * (1.0f - TINYF) + TINYF);
    return -__logf(-__logf(u));
}

__global__ void __launch_bounds__(BT, 1)
kinetic_euler_kernel(const float* __restrict__ logits,
                     const float* __restrict__ source_p,
                     const int*   __restrict__ x_t,
                     const float* __restrict__ t,
                     float*       __restrict__ out) {
    const int n    = blockIdx.x;     // token 0..63
    const int tid  = threadIdx.x;    // 0..511
    const int wid  = tid >> 5;       // 0..15
    const int lane = tid & 31;

    __shared__ unsigned long long wKey[16];
    __shared__ float              wSum[16];

    const float* lrow = logits + n * V;
    float*       orow = out    + n * V;
    const int    v0   = tid;         // element pair: tid, tid+512
    const int    v1   = tid + BT;

    // zero-fill (one float2 per thread position pair)
    orow[v0] = 0.0f;
    orow[v1] = 0.0f;

    // source_p sum: 2 loads per thread
    float psum = source_p[v0] + source_p[v1];

    // two independent gumbel chains (ILP)
    float a0 = lrow[v0] + jax_gumbel((uint32_t)(n * V + v0));
    float a1 = lrow[v1] + jax_gumbel((uint32_t)(n * V + v1));

    // pack both candidates; keep the per-thread winner (v0 < v1, so on ties
    // the packed compare naturally prefers v0 via larger 1023-idx)
    uint32_t o0 = __float_as_uint(a0);
    o0 = (o0 & 0x80000000u) ? ~o0 : (o0 | 0x80000000u);
    uint32_t o1 = __float_as_uint(a1);
    o1 = (o1 & 0x80000000u) ? ~o1 : (o1 | 0x80000000u);
    unsigned long long k0 =
        ((unsigned long long)o0 << 32) | (unsigned int)(V - 1 - v0);
    unsigned long long k1 =
        ((unsigned long long)o1 << 32) | (unsigned int)(V - 1 - v1);
    unsigned long long key = (k1 > k0) ? k1 : k0;

    // warp reduce: u64 max + float sum
#pragma unroll
    for (int off = 16; off > 0; off >>= 1) {
        unsigned long long k2 = __shfl_xor_sync(0xFFFFFFFFu, key, off);
        if (k2 > key) key = k2;
        psum += __shfl_xor_sync(0xFFFFFFFFu, psum, off);
    }
    if (lane == 0) { wKey[wid] = key; wSum[wid] = psum; }
    __syncthreads();

    // warp 0 reduces the 16 per-warp partials and finalizes
    if (wid == 0) {
        key  = (lane < 16) ? wKey[lane] : 0ULL;
        psum = (lane < 16) ? wSum[lane] : 0.0f;
#pragma unroll
        for (int off = 8; off > 0; off >>= 1) {
            unsigned long long k2 = __shfl_xor_sync(0xFFFFFFFFu, key, off);
            if (k2 > key) key = k2;
            psum += __shfl_xor_sync(0xFFFFFFFFu, psum, off);
        }
        if (lane == 0) {
            float S  = psum;
            int x1   = V - 1 - (int)(key & 0xFFFFFFFFu);
            int xti  = __ldg(x_t + n);
            if (x1 != xti) {
                float k  = __ldg(t);
                float si = __ldg(source_p + xti) / S;      // sp[x_t]
                float sj = __ldg(source_p + x1)  / S;      // sp[x1]
                float denom = (1.0f - k) * sj + k + EPSV;  // p_t[x1]+EPS
                float w = si / denom;
                orow[x1]  = w;     // off-diagonal jump rate
                orow[xti] = -w;    // diagonal correction (row sums to zero)
            }
            // x_t == x1: row stays all-zero
        }
    }
}

extern "C" void kernel_launch(void* const* d_in, const int* in_sizes, int n_in,
                              void* d_out, int out_size) {
    const float* logits   = (const float*)d_in[0];
    const float* source_p = (const float*)d_in[1];
    const int*   x_t      = (const int*)  d_in[2];
    const float* t        = (const float*)d_in[3];
    float*       out      = (float*)d_out;
    kinetic_euler_kernel<<<NTOK, BT>>>(logits, source_p, x_t, t, out);
}